// round 1
// baseline (speedup 1.0000x reference)
#include <cuda_runtime.h>
#include <math.h>

#define B_SZ 4
#define S_LEN 4096
#define E_SZ 768
#define H_SZ 64

// Scratch: Q,K stored transposed [b][h][s]; V natural [b][s][h].
__device__ float g_qt[B_SZ * H_SZ * S_LEN];
__device__ float g_kt[B_SZ * H_SZ * S_LEN];
__device__ float g_v [B_SZ * S_LEN * H_SZ];

// ---------------------------------------------------------------------------
// Kernel 1: QKV projection. grid = (16384/128, 3), 256 threads.
// C[s][h] = sum_e x[s][e] * W[h][e].  BM=128, BN=64, BK=16, thread tile 8x4.
// ---------------------------------------------------------------------------
__global__ __launch_bounds__(256) void qkv_kernel(
    const float* __restrict__ x,
    const float* __restrict__ Wq,
    const float* __restrict__ Wk,
    const float* __restrict__ Wv)
{
    const int wsel = blockIdx.y;
    const float* __restrict__ W = (wsel == 0) ? Wq : (wsel == 1) ? Wk : Wv;

    __shared__ float xs[16 * 129];   // x tile transposed [k][m], pad 129 (conflict-free)
    __shared__ float ws[64 * 16];    // W tile [h][k]

    const int tid = threadIdx.x;
    const int tx = tid & 15;         // row lane (8 rows, stride 16)
    const int ty = tid >> 4;         // col group (4 cols)
    const int rowBase = blockIdx.x * 128;

    float acc[8][4];
#pragma unroll
    for (int i = 0; i < 8; i++)
#pragma unroll
        for (int j = 0; j < 4; j++) acc[i][j] = 0.f;

    for (int kb = 0; kb < E_SZ; kb += 16) {
#pragma unroll
        for (int p = 0; p < 8; p++) {
            int lin = p * 256 + tid;
            int r = lin >> 4, c = lin & 15;
            xs[c * 129 + r] = x[(size_t)(rowBase + r) * E_SZ + kb + c];
        }
#pragma unroll
        for (int p = 0; p < 4; p++) {
            int lin = p * 256 + tid;
            int r = lin >> 4, c = lin & 15;
            ws[r * 16 + c] = W[r * E_SZ + kb + c];
        }
        __syncthreads();
#pragma unroll
        for (int k = 0; k < 16; k++) {
            float a[8], bb[4];
#pragma unroll
            for (int i = 0; i < 8; i++) a[i] = xs[k * 129 + tx + 16 * i];
#pragma unroll
            for (int j = 0; j < 4; j++) bb[j] = ws[(4 * ty + j) * 16 + k];
#pragma unroll
            for (int i = 0; i < 8; i++)
#pragma unroll
                for (int j = 0; j < 4; j++)
                    acc[i][j] = fmaf(a[i], bb[j], acc[i][j]);
        }
        __syncthreads();
    }

    if (wsel < 2) {
        // store transposed: dst[b][h][s]
        float* dst = (wsel == 0) ? g_qt : g_kt;
        const int b = rowBase >> 12;          // 4096 rows per batch, BM divides 4096
        const int s0 = rowBase & 4095;
#pragma unroll
        for (int j = 0; j < 4; j++) {
            int h = 4 * ty + j;
#pragma unroll
            for (int i = 0; i < 8; i++)
                dst[(b * H_SZ + h) * S_LEN + s0 + tx + 16 * i] = acc[i][j];
        }
    } else {
        // store natural: g_v[s][h]
#pragma unroll
        for (int i = 0; i < 8; i++) {
            int r = rowBase + tx + 16 * i;
            float4 v = make_float4(acc[i][0], acc[i][1], acc[i][2], acc[i][3]);
            *reinterpret_cast<float4*>(&g_v[(size_t)r * H_SZ + 4 * ty]) = v;
        }
    }
}

// ---------------------------------------------------------------------------
// Kernel 2: flash attention with floor(QK^T/8) scores, fp32 online softmax.
// grid = (4096/64, 4), 256 threads. Tiles: TQ=TK=64, thread tile 4x4.
// Smem: Qt[64][64] (h-major), KtPs[64][64] (K tile h-major, reused as P[q][k]),
// Vs[64][64] (k-major).  Exactly 48 KB.
// ---------------------------------------------------------------------------
__global__ __launch_bounds__(256) void flash_kernel(float* __restrict__ out)
{
    __shared__ float Qt  [64 * 64];
    __shared__ float KtPs[64 * 64];
    __shared__ float Vs  [64 * 64];

    const int tid = threadIdx.x;
    const int tx = tid & 15;     // 4 head/k columns
    const int ty = tid >> 4;     // 4 q rows
    const int b = blockIdx.y;
    const int q0 = blockIdx.x * 64;

    // load Q tile (already transposed in gmem): Qt[h][q_local]
#pragma unroll
    for (int p = 0; p < 4; p++) {
        int f = p * 256 + tid;
        int row = f >> 4, c4 = f & 15;
        *reinterpret_cast<float4*>(&Qt[row * 64 + c4 * 4]) =
            *reinterpret_cast<const float4*>(&g_qt[(size_t)(b * H_SZ + row) * S_LEN + q0 + c4 * 4]);
    }

    float m[4], l[4], o[4][4];
#pragma unroll
    for (int i = 0; i < 4; i++) {
        m[i] = -1e30f; l[i] = 0.f;
#pragma unroll
        for (int j = 0; j < 4; j++) o[i][j] = 0.f;
    }

    for (int k0 = 0; k0 < S_LEN; k0 += 64) {
        __syncthreads();   // previous PV done (and Qt load complete on first iter)
#pragma unroll
        for (int p = 0; p < 4; p++) {
            int f = p * 256 + tid;
            int row = f >> 4, c4 = f & 15;
            *reinterpret_cast<float4*>(&KtPs[row * 64 + c4 * 4]) =
                *reinterpret_cast<const float4*>(&g_kt[(size_t)(b * H_SZ + row) * S_LEN + k0 + c4 * 4]);
            *reinterpret_cast<float4*>(&Vs[row * 64 + c4 * 4]) =
                *reinterpret_cast<const float4*>(&g_v[(size_t)(b * S_LEN + k0 + row) * H_SZ + c4 * 4]);
        }
        __syncthreads();

        // ---- S = Q K^T (outer product over h; Q reads broadcast, K reads conflict-free)
        float acc[4][4];
#pragma unroll
        for (int i = 0; i < 4; i++)
#pragma unroll
            for (int j = 0; j < 4; j++) acc[i][j] = 0.f;

#pragma unroll 16
        for (int h = 0; h < 64; h++) {
            float4 qv = *reinterpret_cast<const float4*>(&Qt[h * 64 + 4 * ty]);
            float4 kv = *reinterpret_cast<const float4*>(&KtPs[h * 64 + 4 * tx]);
            float qa[4] = {qv.x, qv.y, qv.z, qv.w};
            float ka[4] = {kv.x, kv.y, kv.z, kv.w};
#pragma unroll
            for (int i = 0; i < 4; i++)
#pragma unroll
                for (int j = 0; j < 4; j++)
                    acc[i][j] = fmaf(qa[i], ka[j], acc[i][j]);
        }

        // ---- floor + online softmax (row reductions across 16-lane tx groups)
        float p_[4][4];
#pragma unroll
        for (int i = 0; i < 4; i++) {
            float rm = -1e30f;
#pragma unroll
            for (int j = 0; j < 4; j++) {
                acc[i][j] = floorf(acc[i][j] * 0.125f);
                rm = fmaxf(rm, acc[i][j]);
            }
#pragma unroll
            for (int s = 1; s < 16; s <<= 1)
                rm = fmaxf(rm, __shfl_xor_sync(0xffffffffu, rm, s));
            float mn = fmaxf(m[i], rm);
            float alpha = __expf(m[i] - mn);
            m[i] = mn;
            float rs = 0.f;
#pragma unroll
            for (int j = 0; j < 4; j++) {
                p_[i][j] = __expf(acc[i][j] - mn);
                rs += p_[i][j];
            }
#pragma unroll
            for (int s = 1; s < 16; s <<= 1)
                rs += __shfl_xor_sync(0xffffffffu, rs, s);
            l[i] = l[i] * alpha + rs;
#pragma unroll
            for (int j = 0; j < 4; j++) o[i][j] *= alpha;
        }

        __syncthreads();   // everyone done reading K tile
        // write P[q][k] into the K buffer (conflict-free float4 stores)
#pragma unroll
        for (int i = 0; i < 4; i++) {
            float4 pv = make_float4(p_[i][0], p_[i][1], p_[i][2], p_[i][3]);
            *reinterpret_cast<float4*>(&KtPs[(4 * ty + i) * 64 + 4 * tx]) = pv;
        }
        __syncthreads();

        // ---- O += P V  (P reads broadcast, V reads conflict-free)
#pragma unroll 4
        for (int kc = 0; kc < 16; kc++) {
            float pr[4][4];
#pragma unroll
            for (int i = 0; i < 4; i++) {
                float4 t = *reinterpret_cast<const float4*>(&KtPs[(4 * ty + i) * 64 + kc * 4]);
                pr[i][0] = t.x; pr[i][1] = t.y; pr[i][2] = t.z; pr[i][3] = t.w;
            }
#pragma unroll
            for (int kk = 0; kk < 4; kk++) {
                float4 vv = *reinterpret_cast<const float4*>(&Vs[(kc * 4 + kk) * 64 + 4 * tx]);
                float va[4] = {vv.x, vv.y, vv.z, vv.w};
#pragma unroll
                for (int i = 0; i < 4; i++)
#pragma unroll
                    for (int j = 0; j < 4; j++)
                        o[i][j] = fmaf(pr[i][kk], va[j], o[i][j]);
            }
        }
    }

    // ---- epilogue: normalize and store [b][q][h]
#pragma unroll
    for (int i = 0; i < 4; i++) {
        float inv = 1.0f / l[i];
        float4 r = make_float4(o[i][0] * inv, o[i][1] * inv, o[i][2] * inv, o[i][3] * inv);
        int q = q0 + 4 * ty + i;
        *reinterpret_cast<float4*>(&out[(size_t)(b * S_LEN + q) * H_SZ + 4 * tx]) = r;
    }
}

// ---------------------------------------------------------------------------
extern "C" void kernel_launch(void* const* d_in, const int* in_sizes, int n_in,
                              void* d_out, int out_size)
{
    const float* x  = (const float*)d_in[0];
    const float* Wq = (const float*)d_in[1];
    const float* Wk = (const float*)d_in[2];
    const float* Wv = (const float*)d_in[3];
    float* out = (float*)d_out;

    qkv_kernel<<<dim3(128, 3), 256>>>(x, Wq, Wk, Wv);
    flash_kernel<<<dim3(S_LEN / 64, B_SZ), 256>>>(out);
}

// round 2
// speedup vs baseline: 1.0814x; 1.0814x over previous
#include <cuda_runtime.h>
#include <cstdint>
#include <math.h>

#define B_SZ 4
#define S_LEN 4096
#define E_SZ 768
#define H_SZ 64

typedef unsigned long long u64;

// Scratch: Q,K natural [b][s][h]; V transposed [b][h][s].
__device__ float g_q [B_SZ * S_LEN * H_SZ];
__device__ float g_k [B_SZ * S_LEN * H_SZ];
__device__ float g_vt[B_SZ * H_SZ * S_LEN];

// ---- packed fp32 helpers -------------------------------------------------
__device__ __forceinline__ void fma2(u64 &acc, double a, double b) {
    asm("fma.rn.f32x2 %0, %1, %2, %0;"
        : "+l"(acc)
        : "l"(__double_as_longlong(a)), "l"(__double_as_longlong(b)));
}
__device__ __forceinline__ u64 dup2(float v) {
    u64 r; asm("mov.b64 %0, {%1,%1};" : "=l"(r) : "f"(v)); return r;
}
__device__ __forceinline__ void mul2(u64 &acc, u64 s) {
    asm("mul.rn.f32x2 %0, %0, %1;" : "+l"(acc) : "l"(s));
}
__device__ __forceinline__ float2 unpack2(u64 v) {
    float2 f; asm("mov.b64 {%0,%1}, %2;" : "=f"(f.x), "=f"(f.y) : "l"(v)); return f;
}
__device__ __forceinline__ void cp16(uint32_t dst, const float* src) {
    asm volatile("cp.async.cg.shared.global [%0], [%1], 16;" :: "r"(dst), "l"(src));
}

// ---------------------------------------------------------------------------
// Kernel 1: QKV projection. grid=(128,3), 256 thr. C[s][h]=sum_e x[s][e]W[h][e]
// BM=128, BN=64, BK=32; thread tile 8x4; f32x2 packed along E.
// ---------------------------------------------------------------------------
__global__ __launch_bounds__(256, 1) void qkv_kernel(
    const float* __restrict__ x,
    const float* __restrict__ Wq,
    const float* __restrict__ Wk,
    const float* __restrict__ Wv)
{
    const int wsel = blockIdx.y;
    const float* __restrict__ W = (wsel == 0) ? Wq : (wsel == 1) ? Wk : Wv;

    __shared__ float xs[128 * 36];
    __shared__ float ws[64 * 36];

    const int tid = threadIdx.x;
    const int tx = tid & 15;     // h cols: tx + 16j
    const int ty = tid >> 4;     // q rows: 8ty + i
    const int rowBase = blockIdx.x * 128;

    u64 acc[8][4];
#pragma unroll
    for (int i = 0; i < 8; i++)
#pragma unroll
        for (int j = 0; j < 4; j++) acc[i][j] = 0ull;

    for (int kb = 0; kb < E_SZ; kb += 32) {
#pragma unroll
        for (int p = 0; p < 4; p++) {
            int f = p * 256 + tid;
            int r = f >> 3, c = f & 7;
            *reinterpret_cast<float4*>(&xs[r * 36 + 4 * c]) =
                *reinterpret_cast<const float4*>(&x[(size_t)(rowBase + r) * E_SZ + kb + 4 * c]);
        }
#pragma unroll
        for (int p = 0; p < 2; p++) {
            int f = p * 256 + tid;
            int r = f >> 3, c = f & 7;
            *reinterpret_cast<float4*>(&ws[r * 36 + 4 * c]) =
                *reinterpret_cast<const float4*>(&W[(size_t)r * E_SZ + kb + 4 * c]);
        }
        __syncthreads();
#pragma unroll 4
        for (int c = 0; c < 8; c++) {
            double2 xd[8], wd[4];
#pragma unroll
            for (int i = 0; i < 8; i++)
                xd[i] = *reinterpret_cast<const double2*>(&xs[(8 * ty + i) * 36 + 4 * c]);
#pragma unroll
            for (int j = 0; j < 4; j++)
                wd[j] = *reinterpret_cast<const double2*>(&ws[(tx + 16 * j) * 36 + 4 * c]);
#pragma unroll
            for (int i = 0; i < 8; i++)
#pragma unroll
                for (int j = 0; j < 4; j++) {
                    fma2(acc[i][j], xd[i].x, wd[j].x);
                    fma2(acc[i][j], xd[i].y, wd[j].y);
                }
        }
        __syncthreads();
    }

    float r_[8][4];
#pragma unroll
    for (int i = 0; i < 8; i++)
#pragma unroll
        for (int j = 0; j < 4; j++) {
            float2 f = unpack2(acc[i][j]);
            r_[i][j] = f.x + f.y;
        }

    const int b = rowBase >> 12;
    const int s0 = rowBase & 4095;
    if (wsel < 2) {
        float* dst = (wsel == 0) ? g_q : g_k;
#pragma unroll
        for (int i = 0; i < 8; i++)
#pragma unroll
            for (int j = 0; j < 4; j++)
                dst[(size_t)(b * S_LEN + s0 + 8 * ty + i) * H_SZ + tx + 16 * j] = r_[i][j];
    } else {
        // V transposed: g_vt[b][h][s]; 8 consecutive s per thread -> 2x float4
#pragma unroll
        for (int j = 0; j < 4; j++) {
            int h = tx + 16 * j;
            float* dst = &g_vt[(size_t)(b * H_SZ + h) * S_LEN + s0 + 8 * ty];
            *reinterpret_cast<float4*>(dst) = make_float4(r_[0][j], r_[1][j], r_[2][j], r_[3][j]);
            *reinterpret_cast<float4*>(dst + 4) = make_float4(r_[4][j], r_[5][j], r_[6][j], r_[7][j]);
        }
    }
}

// ---------------------------------------------------------------------------
// Kernel 2: flash attention, floor(QK^T/8) scores, f32x2-packed GEMMs.
// grid=(32,4), 256 thr. TQ=128, TK=64. Double-buffered K/V via cp.async.
// Smem (floats): Qs[128*68] @0 | Ks[2][64*68] @8704 | Vt[2][64*68] @17408 |
//                Pb[128*68] @26112.  Total 139264 B (dynamic).
// ---------------------------------------------------------------------------
#define QS_OFF 0
#define KS_OFF 8704
#define VT_OFF 17408
#define PB_OFF 26112
#define BUF_STRIDE 4352
#define SMEM_BYTES (34816 * 4)

__global__ __launch_bounds__(256, 1) void flash_kernel(float* __restrict__ out)
{
    extern __shared__ float sm[];
    const int tid = threadIdx.x;
    const int tx = tid & 15;     // k cols (tx+16j) / h cols (tx+16j)
    const int ty = tid >> 4;     // q rows 8ty+i
    const int b = blockIdx.y;
    const int q0 = blockIdx.x * 128;
    const uint32_t smb = (uint32_t)__cvta_generic_to_shared(sm);

    // prologue: async-load tile 0 (K & V), then Q
    {
#pragma unroll
        for (int p = 0; p < 4; p++) {
            int f = p * 256 + tid;
            int r = f >> 4, c = f & 15;
            cp16(smb + (KS_OFF + r * 68 + 4 * c) * 4,
                 &g_k[(size_t)(b * S_LEN + r) * H_SZ + 4 * c]);
            cp16(smb + (VT_OFF + r * 68 + 4 * c) * 4,
                 &g_vt[(size_t)(b * H_SZ + r) * S_LEN + 4 * c]);
        }
        asm volatile("cp.async.commit_group;");
    }
#pragma unroll
    for (int p = 0; p < 8; p++) {
        int f = p * 256 + tid;
        int r = f >> 4, c = f & 15;
        *reinterpret_cast<float4*>(&sm[QS_OFF + r * 68 + 4 * c]) =
            *reinterpret_cast<const float4*>(&g_q[(size_t)(b * S_LEN + q0 + r) * H_SZ + 4 * c]);
    }

    float m[8], l[8];
    u64 o2[8][4];
#pragma unroll
    for (int i = 0; i < 8; i++) {
        m[i] = -1e30f; l[i] = 0.f;
#pragma unroll
        for (int j = 0; j < 4; j++) o2[i][j] = 0ull;
    }

    for (int t = 0; t < S_LEN / 64; t++) {
        __syncthreads();                     // prev PV / P-buffer fully consumed
        if (t + 1 < S_LEN / 64) {
            const int buf = (t + 1) & 1;
            const int k0n = (t + 1) * 64;
#pragma unroll
            for (int p = 0; p < 4; p++) {
                int f = p * 256 + tid;
                int r = f >> 4, c = f & 15;
                cp16(smb + (KS_OFF + buf * BUF_STRIDE + r * 68 + 4 * c) * 4,
                     &g_k[(size_t)(b * S_LEN + k0n + r) * H_SZ + 4 * c]);
                cp16(smb + (VT_OFF + buf * BUF_STRIDE + r * 68 + 4 * c) * 4,
                     &g_vt[(size_t)(b * H_SZ + r) * S_LEN + k0n + 4 * c]);
            }
            asm volatile("cp.async.commit_group;");
            asm volatile("cp.async.wait_group 1;");
        } else {
            asm volatile("cp.async.wait_group 0;");
        }
        __syncthreads();                     // current K/V tile visible

        const float* Ks = sm + KS_OFF + (t & 1) * BUF_STRIDE;
        const float* Vt = sm + VT_OFF + (t & 1) * BUF_STRIDE;
        float* Pb = sm + PB_OFF;

        // ---- S = Q K^T : pack along h
        u64 acc[8][4];
#pragma unroll
        for (int i = 0; i < 8; i++)
#pragma unroll
            for (int j = 0; j < 4; j++) acc[i][j] = 0ull;

#pragma unroll 4
        for (int c = 0; c < 16; c++) {
            double2 qd[8], kd[4];
#pragma unroll
            for (int i = 0; i < 8; i++)
                qd[i] = *reinterpret_cast<const double2*>(&sm[QS_OFF + (8 * ty + i) * 68 + 4 * c]);
#pragma unroll
            for (int j = 0; j < 4; j++)
                kd[j] = *reinterpret_cast<const double2*>(&Ks[(tx + 16 * j) * 68 + 4 * c]);
#pragma unroll
            for (int i = 0; i < 8; i++)
#pragma unroll
                for (int j = 0; j < 4; j++) {
                    fma2(acc[i][j], qd[i].x, kd[j].x);
                    fma2(acc[i][j], qd[i].y, kd[j].y);
                }
        }

        // ---- floor + online softmax (row reduction over 16 tx lanes)
#pragma unroll
        for (int i = 0; i < 8; i++) {
            float s[4];
            float rm = -1e30f;
#pragma unroll
            for (int j = 0; j < 4; j++) {
                float2 f = unpack2(acc[i][j]);
                s[j] = floorf((f.x + f.y) * 0.125f);
                rm = fmaxf(rm, s[j]);
            }
#pragma unroll
            for (int d = 1; d < 16; d <<= 1)
                rm = fmaxf(rm, __shfl_xor_sync(0xffffffffu, rm, d));
            float mn = fmaxf(m[i], rm);
            float alpha = __expf(m[i] - mn);
            m[i] = mn;
            float pv[4];
            float rs = 0.f;
#pragma unroll
            for (int j = 0; j < 4; j++) {
                pv[j] = __expf(s[j] - mn);
                rs += pv[j];
            }
#pragma unroll
            for (int d = 1; d < 16; d <<= 1)
                rs += __shfl_xor_sync(0xffffffffu, rs, d);
            l[i] = l[i] * alpha + rs;
            u64 a2 = dup2(alpha);
#pragma unroll
            for (int j = 0; j < 4; j++) mul2(o2[i][j], a2);
#pragma unroll
            for (int j = 0; j < 4; j++)
                Pb[(8 * ty + i) * 68 + tx + 16 * j] = pv[j];
        }
        __syncthreads();                     // P tile complete

        // ---- O += P V : pack along k
#pragma unroll 4
        for (int c = 0; c < 16; c++) {
            double2 pd[8], vd[4];
#pragma unroll
            for (int i = 0; i < 8; i++)
                pd[i] = *reinterpret_cast<const double2*>(&Pb[(8 * ty + i) * 68 + 4 * c]);
#pragma unroll
            for (int j = 0; j < 4; j++)
                vd[j] = *reinterpret_cast<const double2*>(&Vt[(tx + 16 * j) * 68 + 4 * c]);
#pragma unroll
            for (int i = 0; i < 8; i++)
#pragma unroll
                for (int j = 0; j < 4; j++) {
                    fma2(o2[i][j], pd[i].x, vd[j].x);
                    fma2(o2[i][j], pd[i].y, vd[j].y);
                }
        }
    }

    // ---- epilogue
#pragma unroll
    for (int i = 0; i < 8; i++) {
        float inv = 1.0f / l[i];
#pragma unroll
        for (int j = 0; j < 4; j++) {
            float2 f = unpack2(o2[i][j]);
            out[(size_t)(b * S_LEN + q0 + 8 * ty + i) * H_SZ + tx + 16 * j] = (f.x + f.y) * inv;
        }
    }
}

// ---------------------------------------------------------------------------
extern "C" void kernel_launch(void* const* d_in, const int* in_sizes, int n_in,
                              void* d_out, int out_size)
{
    const float* x  = (const float*)d_in[0];
    const float* Wq = (const float*)d_in[1];
    const float* Wk = (const float*)d_in[2];
    const float* Wv = (const float*)d_in[3];
    float* out = (float*)d_out;

    cudaFuncSetAttribute(flash_kernel, cudaFuncAttributeMaxDynamicSharedMemorySize, SMEM_BYTES);

    qkv_kernel<<<dim3(128, 3), 256>>>(x, Wq, Wk, Wv);
    flash_kernel<<<dim3(S_LEN / 128, B_SZ), 256, SMEM_BYTES>>>(out);
}